// round 1
// baseline (speedup 1.0000x reference)
#include <cuda_runtime.h>
#include <cstdint>
#include <cstddef>

#define BB 8
#define TT 2048
#define CC 1024
#define HH 128

// Scratch for Q/K/V projections (8 MB each). __device__ globals — no runtime alloc.
__device__ float g_q[BB * TT * HH];
__device__ float g_k[BB * TT * HH];
__device__ float g_v[BB * TT * HH];

// ---------------------------------------------------------------------------
// QKV projection GEMM: out[m][n] = sum_k X[m][k] * W[k][n]
// M = B*T = 16384, K = C = 1024, N = H = 128.
// Block tile 128(M) x 128(N), BK = 16, 256 threads, 8x8 per thread.
// blockIdx.z selects projection (Wq/Wk/Wv -> g_q/g_k/g_v).
// ---------------------------------------------------------------------------
__global__ __launch_bounds__(256) void qkv_gemm_kernel(
    const float* __restrict__ X,
    const float* __restrict__ Wq,
    const float* __restrict__ Wk,
    const float* __restrict__ Wv)
{
    __shared__ float sA[16][128 + 4];   // sA[k][m]  (X transposed)
    __shared__ float sB[16][128 + 4];   // sB[k][n]  (W as-is)

    const int mblk = blockIdx.y;
    const int proj = blockIdx.z;
    const float* __restrict__ W = (proj == 0) ? Wq : (proj == 1) ? Wk : Wv;
    float* __restrict__ out     = (proj == 0) ? g_q : (proj == 1) ? g_k : g_v;

    const int tid = threadIdx.x;
    const int ty  = tid >> 4;    // 0..15
    const int tx  = tid & 15;    // 0..15

    float acc[8][8];
#pragma unroll
    for (int i = 0; i < 8; i++)
#pragma unroll
        for (int jj = 0; jj < 8; jj++) acc[i][jj] = 0.0f;

    for (int k0 = 0; k0 < CC; k0 += 16) {
        // Load X tile [128 m][16 k], store transposed into sA[k][m].
#pragma unroll
        for (int it = 0; it < 2; it++) {
            int f  = tid + it * 256;         // 512 float4 total
            int m  = f >> 2;
            int c4 = f & 3;
            float4 xv = *(const float4*)(X + (size_t)(mblk * 128 + m) * CC + k0 + c4 * 4);
            sA[c4 * 4 + 0][m] = xv.x;
            sA[c4 * 4 + 1][m] = xv.y;
            sA[c4 * 4 + 2][m] = xv.z;
            sA[c4 * 4 + 3][m] = xv.w;
        }
        // Load W tile [16 k][128 n] directly.
#pragma unroll
        for (int it = 0; it < 2; it++) {
            int f  = tid + it * 256;
            int kk = f >> 5;
            int c4 = f & 31;
            float4 wv = *(const float4*)(W + (size_t)(k0 + kk) * HH + c4 * 4);
            *(float4*)&sB[kk][c4 * 4] = wv;
        }
        __syncthreads();

#pragma unroll
        for (int kk = 0; kk < 16; kk++) {
            float a[8], bb[8];
            *(float4*)&a[0]  = *(const float4*)&sA[kk][ty * 8];
            *(float4*)&a[4]  = *(const float4*)&sA[kk][ty * 8 + 4];
            *(float4*)&bb[0] = *(const float4*)&sB[kk][tx * 8];
            *(float4*)&bb[4] = *(const float4*)&sB[kk][tx * 8 + 4];
#pragma unroll
            for (int i = 0; i < 8; i++)
#pragma unroll
                for (int jj = 0; jj < 8; jj++)
                    acc[i][jj] += a[i] * bb[jj];
        }
        __syncthreads();
    }

    // Write 8x8 result tile.
#pragma unroll
    for (int i = 0; i < 8; i++) {
        size_t row = (size_t)(mblk * 128 + ty * 8 + i);
        float* dst = out + row * HH + tx * 8;
        float4 o0 = make_float4(acc[i][0], acc[i][1], acc[i][2], acc[i][3]);
        float4 o1 = make_float4(acc[i][4], acc[i][5], acc[i][6], acc[i][7]);
        *(float4*)dst       = o0;
        *(float4*)(dst + 4) = o1;
    }
}

// ---------------------------------------------------------------------------
// Causal flash attention, fp32.
// Grid: (T/64, B). Block: 256 threads (16x16).
// Q tile: 64 rows x 128. KV tiles: 64 x 128, streamed with online softmax.
// Thread (ty,tx): S fragment rows 4ty..4ty+3, cols 4tx..4tx+3;
//                 O fragment rows 4ty..4ty+3, cols 8tx..8tx+7.
// ---------------------------------------------------------------------------
#define QPAD 132          // 128 + 4 (float4-aligned padded row)
#define PPAD 68           // 64 + 4

__global__ __launch_bounds__(256) void attn_kernel(float* __restrict__ Out)
{
    extern __shared__ float smem[];
    float* sQ = smem;                    // 64 * 132
    float* sK = sQ + 64 * QPAD;          // 64 * 132
    float* sV = sK + 64 * QPAD;          // 64 * 132
    float* sP = sV + 64 * QPAD;          // 64 * 68

    const int qt  = blockIdx.x;
    const int b   = blockIdx.y;
    const int tid = threadIdx.x;
    const int ty  = tid >> 4;
    const int tx  = tid & 15;

    const float scale = 0.08838834764831845f;  // 1/sqrt(128)

    // Load Q tile (64 x 128).
    const float* Qb = g_q + ((size_t)b * TT + (size_t)qt * 64) * HH;
#pragma unroll
    for (int it = 0; it < 8; it++) {
        int f  = tid + it * 256;          // 2048 float4
        int r  = f >> 5;
        int c4 = f & 31;
        *(float4*)&sQ[r * QPAD + c4 * 4] = *(const float4*)(Qb + r * HH + c4 * 4);
    }

    float m_i[4], l_i[4], acc[4][8];
#pragma unroll
    for (int i = 0; i < 4; i++) {
        m_i[i] = -1e30f;
        l_i[i] = 0.0f;
#pragma unroll
        for (int c = 0; c < 8; c++) acc[i][c] = 0.0f;
    }

    for (int j = 0; j <= qt; j++) {
        __syncthreads();   // previous iteration's sK/sV/sP reads done

        const float* Kb = g_k + ((size_t)b * TT + (size_t)j * 64) * HH;
        const float* Vb = g_v + ((size_t)b * TT + (size_t)j * 64) * HH;
#pragma unroll
        for (int it = 0; it < 8; it++) {
            int f  = tid + it * 256;
            int r  = f >> 5;
            int c4 = f & 31;
            *(float4*)&sK[r * QPAD + c4 * 4] = *(const float4*)(Kb + r * HH + c4 * 4);
            *(float4*)&sV[r * QPAD + c4 * 4] = *(const float4*)(Vb + r * HH + c4 * 4);
        }
        __syncthreads();

        // S = Q K^T (4x4 fragment).
        float s[4][4];
#pragma unroll
        for (int i = 0; i < 4; i++)
#pragma unroll
            for (int c = 0; c < 4; c++) s[i][c] = 0.0f;

#pragma unroll 8
        for (int d = 0; d < HH; d += 4) {
            float4 qf[4], kf[4];
#pragma unroll
            for (int i = 0; i < 4; i++)
                qf[i] = *(const float4*)&sQ[(ty * 4 + i) * QPAD + d];
#pragma unroll
            for (int c = 0; c < 4; c++)
                kf[c] = *(const float4*)&sK[(tx * 4 + c) * QPAD + d];
#pragma unroll
            for (int i = 0; i < 4; i++)
#pragma unroll
                for (int c = 0; c < 4; c++)
                    s[i][c] += qf[i].x * kf[c].x + qf[i].y * kf[c].y +
                               qf[i].z * kf[c].z + qf[i].w * kf[c].w;
        }

        // Scale + causal mask (diagonal tile only; j<qt tiles are fully valid).
#pragma unroll
        for (int i = 0; i < 4; i++)
#pragma unroll
            for (int c = 0; c < 4; c++) s[i][c] *= scale;

        if (j == qt) {
#pragma unroll
            for (int i = 0; i < 4; i++)
#pragma unroll
                for (int c = 0; c < 4; c++)
                    if (tx * 4 + c > ty * 4 + i) s[i][c] = -1e30f;
        }

        // Online softmax, per row (rows shared by the 16 tx lanes of this ty).
#pragma unroll
        for (int i = 0; i < 4; i++) {
            float rm = fmaxf(fmaxf(s[i][0], s[i][1]), fmaxf(s[i][2], s[i][3]));
#pragma unroll
            for (int off = 8; off > 0; off >>= 1)
                rm = fmaxf(rm, __shfl_xor_sync(0xffffffffu, rm, off, 16));

            float mnew = fmaxf(m_i[i], rm);
            float al   = __expf(m_i[i] - mnew);
            float p0 = __expf(s[i][0] - mnew);
            float p1 = __expf(s[i][1] - mnew);
            float p2 = __expf(s[i][2] - mnew);
            float p3 = __expf(s[i][3] - mnew);
            float rs = (p0 + p1) + (p2 + p3);
#pragma unroll
            for (int off = 8; off > 0; off >>= 1)
                rs += __shfl_xor_sync(0xffffffffu, rs, off, 16);

            l_i[i] = l_i[i] * al + rs;
            m_i[i] = mnew;
#pragma unroll
            for (int c = 0; c < 8; c++) acc[i][c] *= al;

            float4 pv = make_float4(p0, p1, p2, p3);
            *(float4*)&sP[(ty * 4 + i) * PPAD + tx * 4] = pv;
        }
        __syncwarp();  // sP rows are produced & consumed within one warp's ty-group

        // O += P V
#pragma unroll 8
        for (int ss = 0; ss < 64; ss++) {
            float4 va = *(const float4*)&sV[ss * QPAD + tx * 8];
            float4 vb = *(const float4*)&sV[ss * QPAD + tx * 8 + 4];
#pragma unroll
            for (int i = 0; i < 4; i++) {
                float p = sP[(ty * 4 + i) * PPAD + ss];
                acc[i][0] += p * va.x;  acc[i][1] += p * va.y;
                acc[i][2] += p * va.z;  acc[i][3] += p * va.w;
                acc[i][4] += p * vb.x;  acc[i][5] += p * vb.y;
                acc[i][6] += p * vb.z;  acc[i][7] += p * vb.w;
            }
        }
    }

    // Epilogue: O /= l, write out.
#pragma unroll
    for (int i = 0; i < 4; i++) {
        int t = qt * 64 + ty * 4 + i;
        float inv = 1.0f / l_i[i];
        float4 o0 = make_float4(acc[i][0] * inv, acc[i][1] * inv,
                                acc[i][2] * inv, acc[i][3] * inv);
        float4 o1 = make_float4(acc[i][4] * inv, acc[i][5] * inv,
                                acc[i][6] * inv, acc[i][7] * inv);
        float* dst = Out + ((size_t)b * TT + t) * HH + tx * 8;
        *(float4*)dst       = o0;
        *(float4*)(dst + 4) = o1;
    }
}

// ---------------------------------------------------------------------------
extern "C" void kernel_launch(void* const* d_in, const int* in_sizes, int n_in,
                              void* d_out, int out_size)
{
    const float* x  = (const float*)d_in[0];
    const float* Wq = (const float*)d_in[1];
    const float* Wk = (const float*)d_in[2];
    const float* Wv = (const float*)d_in[3];
    float* out = (float*)d_out;

    (void)in_sizes; (void)n_in; (void)out_size;

    // 1) QKV projections: grid (1, M/128, 3)
    dim3 g1(1, (BB * TT) / 128, 3);
    qkv_gemm_kernel<<<g1, 256>>>(x, Wq, Wk, Wv);

    // 2) Causal flash attention: grid (T/64, B)
    const int smem_bytes = (3 * 64 * QPAD + 64 * PPAD) * (int)sizeof(float);
    cudaFuncSetAttribute(attn_kernel,
                         cudaFuncAttributeMaxDynamicSharedMemorySize, smem_bytes);
    attn_kernel<<<dim3(TT / 64, BB), 256, smem_bytes>>>(out);
}

// round 2
// speedup vs baseline: 2.4390x; 2.4390x over previous
#include <cuda_runtime.h>
#include <cstdint>
#include <cstddef>

#define BB 8
#define TT 2048
#define CC 1024
#define HH 128

// Scratch for Q/K/V projections. __device__ globals — no runtime alloc.
__device__ float g_q[BB * TT * HH];
__device__ float g_k[BB * TT * HH];
__device__ float g_v[BB * TT * HH];

// ---------------------------------------------------------------------------
// Helpers
// ---------------------------------------------------------------------------
__device__ __forceinline__ float tf32r(float x) {
    uint32_t u;
    asm("cvt.rna.tf32.f32 %0, %1;" : "=r"(u) : "f"(x));
    return __uint_as_float(u);
}

__device__ __forceinline__ void cp16(uint32_t saddr, const float* gaddr) {
    asm volatile("cp.async.cg.shared.global [%0], [%1], 16;"
                 :: "r"(saddr), "l"(gaddr));
}
__device__ __forceinline__ void cp_commit() {
    asm volatile("cp.async.commit_group;");
}

__device__ __forceinline__ float fex2(float x) {
    float r;
    asm("ex2.approx.f32 %0, %1;" : "=f"(r) : "f"(x));
    return r;
}

// D += A(16x8 tf32) * B(8x8 tf32), fp32 accum.
__device__ __forceinline__ void mma8(float* c, const uint32_t* a,
                                     uint32_t b0, uint32_t b1) {
    asm volatile(
        "mma.sync.aligned.m16n8k8.row.col.f32.tf32.tf32.f32 "
        "{%0,%1,%2,%3}, {%4,%5,%6,%7}, {%8,%9}, {%0,%1,%2,%3};"
        : "+f"(c[0]), "+f"(c[1]), "+f"(c[2]), "+f"(c[3])
        : "r"(a[0]), "r"(a[1]), "r"(a[2]), "r"(a[3]), "r"(b0), "r"(b1));
}

// ---------------------------------------------------------------------------
// QKV projection GEMM (fp32 math, tf32-rna-rounded outputs).
// M = B*T = 16384, K = C = 1024, N = H = 128. Block tile 128x128, BK=16.
// ---------------------------------------------------------------------------
__global__ __launch_bounds__(256) void qkv_gemm_kernel(
    const float* __restrict__ X,
    const float* __restrict__ Wq,
    const float* __restrict__ Wk,
    const float* __restrict__ Wv)
{
    __shared__ float sA[16][128 + 4];
    __shared__ float sB[16][128 + 4];

    const int mblk = blockIdx.y;
    const int proj = blockIdx.z;
    const float* __restrict__ W = (proj == 0) ? Wq : (proj == 1) ? Wk : Wv;
    float* __restrict__ out     = (proj == 0) ? g_q : (proj == 1) ? g_k : g_v;

    const int tid = threadIdx.x;
    const int ty  = tid >> 4;
    const int tx  = tid & 15;

    float acc[8][8];
#pragma unroll
    for (int i = 0; i < 8; i++)
#pragma unroll
        for (int jj = 0; jj < 8; jj++) acc[i][jj] = 0.0f;

    for (int k0 = 0; k0 < CC; k0 += 16) {
#pragma unroll
        for (int it = 0; it < 2; it++) {
            int f  = tid + it * 256;
            int m  = f >> 2;
            int c4 = f & 3;
            float4 xv = *(const float4*)(X + (size_t)(mblk * 128 + m) * CC + k0 + c4 * 4);
            sA[c4 * 4 + 0][m] = xv.x;
            sA[c4 * 4 + 1][m] = xv.y;
            sA[c4 * 4 + 2][m] = xv.z;
            sA[c4 * 4 + 3][m] = xv.w;
        }
#pragma unroll
        for (int it = 0; it < 2; it++) {
            int f  = tid + it * 256;
            int kk = f >> 5;
            int c4 = f & 31;
            float4 wv = *(const float4*)(W + (size_t)(k0 + kk) * HH + c4 * 4);
            *(float4*)&sB[kk][c4 * 4] = wv;
        }
        __syncthreads();

#pragma unroll
        for (int kk = 0; kk < 16; kk++) {
            float a[8], bb[8];
            *(float4*)&a[0]  = *(const float4*)&sA[kk][ty * 8];
            *(float4*)&a[4]  = *(const float4*)&sA[kk][ty * 8 + 4];
            *(float4*)&bb[0] = *(const float4*)&sB[kk][tx * 8];
            *(float4*)&bb[4] = *(const float4*)&sB[kk][tx * 8 + 4];
#pragma unroll
            for (int i = 0; i < 8; i++)
#pragma unroll
                for (int jj = 0; jj < 8; jj++)
                    acc[i][jj] += a[i] * bb[jj];
        }
        __syncthreads();
    }

#pragma unroll
    for (int i = 0; i < 8; i++) {
        size_t row = (size_t)(mblk * 128 + ty * 8 + i);
        float* dst = out + row * HH + tx * 8;
        float4 o0 = make_float4(tf32r(acc[i][0]), tf32r(acc[i][1]),
                                tf32r(acc[i][2]), tf32r(acc[i][3]));
        float4 o1 = make_float4(tf32r(acc[i][4]), tf32r(acc[i][5]),
                                tf32r(acc[i][6]), tf32r(acc[i][7]));
        *(float4*)dst       = o0;
        *(float4*)(dst + 4) = o1;
    }
}

// ---------------------------------------------------------------------------
// Causal flash attention with mma.sync tf32 tensor cores.
// Grid (32, 8): qt = 31 - blockIdx.x (heavy CTAs launch first).
// 128 threads = 4 warps; warp w owns Q rows 16w..16w+15 of a 64-row Q tile.
// KV tiles of 64 rows, double-buffered via cp.async.
// ---------------------------------------------------------------------------
#define KST 132     // Q/K smem row stride: (4g+tg)%32 distinct -> conflict-free
#define VST 136     // V smem row stride:   (8tg+g)%32 distinct -> conflict-free
#define PST 68      // P smem row stride:   (4g+tg)%32 distinct

__global__ __launch_bounds__(128) void attn_mma_kernel(float* __restrict__ Out)
{
    extern __shared__ float smem[];
    float* sQ  = smem;                       // 64*132
    float* sK0 = sQ  + 64 * KST;             // 64*132
    float* sV0 = sK0 + 64 * KST;             // 64*136
    float* sK1 = sV0 + 64 * VST;             // 64*132
    float* sV1 = sK1 + 64 * KST;             // 64*136
    float* sP  = sV1 + 64 * VST;             // 64*68

    const int qt   = (int)gridDim.x - 1 - blockIdx.x;
    const int b    = blockIdx.y;
    const int tid  = threadIdx.x;
    const int wid  = tid >> 5;
    const int lane = tid & 31;
    const int g    = lane >> 2;   // 0..7
    const int tg   = lane & 3;    // 0..3

    const uint32_t sQa  = (uint32_t)__cvta_generic_to_shared(sQ);
    const uint32_t sK0a = (uint32_t)__cvta_generic_to_shared(sK0);
    const uint32_t sV0a = (uint32_t)__cvta_generic_to_shared(sV0);
    const uint32_t sK1a = (uint32_t)__cvta_generic_to_shared(sK1);
    const uint32_t sV1a = (uint32_t)__cvta_generic_to_shared(sV1);

    // --- issue Q load + tile-0 K/V prefetch (async group 0) ---
    const float* Qb = g_q + ((size_t)b * TT + (size_t)qt * 64) * HH;
    const float* Kb = g_k + ((size_t)b * TT) * HH;
    const float* Vb = g_v + ((size_t)b * TT) * HH;
#pragma unroll
    for (int it = 0; it < 16; it++) {
        int f  = tid + it * 128;
        int r  = f >> 5;
        int c4 = f & 31;
        cp16(sQa + (r * KST + c4 * 4) * 4, Qb + r * HH + c4 * 4);
    }
#pragma unroll
    for (int it = 0; it < 16; it++) {
        int f  = tid + it * 128;
        int r  = f >> 5;
        int c4 = f & 31;
        cp16(sK0a + (r * KST + c4 * 4) * 4, Kb + r * HH + c4 * 4);
        cp16(sV0a + (r * VST + c4 * 4) * 4, Vb + r * HH + c4 * 4);
    }
    cp_commit();
    asm volatile("cp.async.wait_group 0;");
    __syncthreads();

    // --- preload Q fragments (invariant across KV tiles) ---
    uint32_t qa[16][4];
#pragma unroll
    for (int ks = 0; ks < 16; ks++) {
        const int r0 = (16 * wid + g) * KST + ks * 8 + tg;
        qa[ks][0] = __float_as_uint(sQ[r0]);
        qa[ks][1] = __float_as_uint(sQ[r0 + 8 * KST]);
        qa[ks][2] = __float_as_uint(sQ[r0 + 4]);
        qa[ks][3] = __float_as_uint(sQ[r0 + 8 * KST + 4]);
    }

    float o[16][4];
#pragma unroll
    for (int n = 0; n < 16; n++)
#pragma unroll
        for (int v = 0; v < 4; v++) o[n][v] = 0.0f;
    float m0 = -1e30f, m1 = -1e30f, l0 = 0.0f, l1 = 0.0f;

    // scale folded into log2 domain: p = 2^(s*SCL - m)
    const float SCL = 0.08838834764831845f * 1.4426950408889634f;

    for (int j = 0; j <= qt; j++) {
        // prefetch next tile into the buffer not used this iteration
        if (j < qt) {
            const float* Kn = g_k + ((size_t)b * TT + (size_t)(j + 1) * 64) * HH;
            const float* Vn = g_v + ((size_t)b * TT + (size_t)(j + 1) * 64) * HH;
            uint32_t ska = ((j + 1) & 1) ? sK1a : sK0a;
            uint32_t sva = ((j + 1) & 1) ? sV1a : sV0a;
#pragma unroll
            for (int it = 0; it < 16; it++) {
                int f  = tid + it * 128;
                int r  = f >> 5;
                int c4 = f & 31;
                cp16(ska + (r * KST + c4 * 4) * 4, Kn + r * HH + c4 * 4);
                cp16(sva + (r * VST + c4 * 4) * 4, Vn + r * HH + c4 * 4);
            }
            cp_commit();
        }
        if (j > 0) {
            if (j < qt) asm volatile("cp.async.wait_group 1;");
            else        asm volatile("cp.async.wait_group 0;");
            __syncthreads();
        }

        const float* kb = (j & 1) ? sK1 : sK0;
        const float* vb = (j & 1) ? sV1 : sV0;

        // ----- S = Q K^T : 8 n-tiles of 8 cols, 16 k-steps -----
        float c[8][4];
#pragma unroll
        for (int n = 0; n < 8; n++)
#pragma unroll
            for (int v = 0; v < 4; v++) c[n][v] = 0.0f;

#pragma unroll
        for (int ks = 0; ks < 16; ks++) {
#pragma unroll
            for (int n = 0; n < 8; n++) {
                const int base = (n * 8 + g) * KST + ks * 8 + tg;
                uint32_t b0 = __float_as_uint(kb[base]);
                uint32_t b1 = __float_as_uint(kb[base + 4]);
                mma8(c[n], qa[ks], b0, b1);
            }
        }

        // ----- scale (log2 domain) + causal mask -----
#pragma unroll
        for (int n = 0; n < 8; n++)
#pragma unroll
            for (int v = 0; v < 4; v++) c[n][v] *= SCL;

        if (j == qt) {
            const int r0 = 16 * wid + g;
            const int r1 = r0 + 8;
#pragma unroll
            for (int n = 0; n < 8; n++) {
                const int col = 8 * n + 2 * tg;
                if (col     > r0) c[n][0] = -1e30f;
                if (col + 1 > r0) c[n][1] = -1e30f;
                if (col     > r1) c[n][2] = -1e30f;
                if (col + 1 > r1) c[n][3] = -1e30f;
            }
        }

        // ----- online softmax (rows r0 = 16w+g, r1 = r0+8) -----
        float rm0 = -1e30f, rm1 = -1e30f;
#pragma unroll
        for (int n = 0; n < 8; n++) {
            rm0 = fmaxf(rm0, fmaxf(c[n][0], c[n][1]));
            rm1 = fmaxf(rm1, fmaxf(c[n][2], c[n][3]));
        }
        rm0 = fmaxf(rm0, __shfl_xor_sync(0xffffffffu, rm0, 1));
        rm0 = fmaxf(rm0, __shfl_xor_sync(0xffffffffu, rm0, 2));
        rm1 = fmaxf(rm1, __shfl_xor_sync(0xffffffffu, rm1, 1));
        rm1 = fmaxf(rm1, __shfl_xor_sync(0xffffffffu, rm1, 2));

        const float m0n = fmaxf(m0, rm0);
        const float m1n = fmaxf(m1, rm1);
        const float a0  = fex2(m0 - m0n);
        const float a1  = fex2(m1 - m1n);

        float rs0 = 0.0f, rs1 = 0.0f;
#pragma unroll
        for (int n = 0; n < 8; n++) {
            c[n][0] = fex2(c[n][0] - m0n);
            c[n][1] = fex2(c[n][1] - m0n);
            c[n][2] = fex2(c[n][2] - m1n);
            c[n][3] = fex2(c[n][3] - m1n);
            rs0 += c[n][0] + c[n][1];
            rs1 += c[n][2] + c[n][3];
        }
        rs0 += __shfl_xor_sync(0xffffffffu, rs0, 1);
        rs0 += __shfl_xor_sync(0xffffffffu, rs0, 2);
        rs1 += __shfl_xor_sync(0xffffffffu, rs1, 1);
        rs1 += __shfl_xor_sync(0xffffffffu, rs1, 2);

        l0 = l0 * a0 + rs0;
        l1 = l1 * a1 + rs1;
        m0 = m0n;
        m1 = m1n;

#pragma unroll
        for (int n = 0; n < 16; n++) {
            o[n][0] *= a0; o[n][1] *= a0;
            o[n][2] *= a1; o[n][3] *= a1;
        }

        // ----- stage P (tf32-rna) to smem for A-operand reload -----
        __syncwarp();
        {
            const int r0 = 16 * wid + g;
#pragma unroll
            for (int n = 0; n < 8; n++) {
                const int col = 8 * n + 2 * tg;
                *(float2*)&sP[r0 * PST + col] =
                    make_float2(tf32r(c[n][0]), tf32r(c[n][1]));
                *(float2*)&sP[(r0 + 8) * PST + col] =
                    make_float2(tf32r(c[n][2]), tf32r(c[n][3]));
            }
        }
        __syncwarp();

        // ----- O += P V : 16 n-tiles of 8 cols, 8 k-steps -----
#pragma unroll
        for (int kk = 0; kk < 8; kk++) {
            uint32_t pa[4];
            const int pr = (16 * wid + g) * PST + kk * 8 + tg;
            pa[0] = __float_as_uint(sP[pr]);
            pa[1] = __float_as_uint(sP[pr + 8 * PST]);
            pa[2] = __float_as_uint(sP[pr + 4]);
            pa[3] = __float_as_uint(sP[pr + 8 * PST + 4]);
#pragma unroll
            for (int n = 0; n < 16; n++) {
                const int base = (kk * 8 + tg) * VST + 8 * n + g;
                uint32_t b0 = __float_as_uint(vb[base]);
                uint32_t b1 = __float_as_uint(vb[base + 4 * VST]);
                mma8(o[n], pa, b0, b1);
            }
        }
        __syncthreads();
    }

    // ----- epilogue: normalize and store -----
    const float inv0 = 1.0f / l0;
    const float inv1 = 1.0f / l1;
    const int r0 = qt * 64 + 16 * wid + g;
    float* p0 = Out + ((size_t)b * TT + r0) * HH;
    float* p1 = p0 + 8 * HH;
#pragma unroll
    for (int n = 0; n < 16; n++) {
        const int col = 8 * n + 2 * tg;
        *(float2*)(p0 + col) = make_float2(o[n][0] * inv0, o[n][1] * inv0);
        *(float2*)(p1 + col) = make_float2(o[n][2] * inv1, o[n][3] * inv1);
    }
}

// ---------------------------------------------------------------------------
extern "C" void kernel_launch(void* const* d_in, const int* in_sizes, int n_in,
                              void* d_out, int out_size)
{
    const float* x  = (const float*)d_in[0];
    const float* Wq = (const float*)d_in[1];
    const float* Wk = (const float*)d_in[2];
    const float* Wv = (const float*)d_in[3];
    float* out = (float*)d_out;

    (void)in_sizes; (void)n_in; (void)out_size;

    dim3 g1(1, (BB * TT) / 128, 3);
    qkv_gemm_kernel<<<g1, 256>>>(x, Wq, Wk, Wv);

    const int smem_bytes = 64 * (3 * KST + 2 * VST + PST) * (int)sizeof(float);
    cudaFuncSetAttribute(attn_mma_kernel,
                         cudaFuncAttributeMaxDynamicSharedMemorySize, smem_bytes);
    attn_mma_kernel<<<dim3(TT / 64, BB), 128, smem_bytes>>>(out);
}

// round 3
// speedup vs baseline: 5.0316x; 2.0630x over previous
#include <cuda_runtime.h>
#include <cstdint>
#include <cstddef>

#define BB 8
#define TT 2048
#define CC 1024
#define HH 128

// Scratch for Q/K/V projections. __device__ globals — no runtime alloc.
__device__ float g_q[BB * TT * HH];
__device__ float g_k[BB * TT * HH];
__device__ float g_v[BB * TT * HH];

// ---------------------------------------------------------------------------
// Helpers
// ---------------------------------------------------------------------------
__device__ __forceinline__ float tf32r(float x) {
    uint32_t u;
    asm("cvt.rna.tf32.f32 %0, %1;" : "=r"(u) : "f"(x));
    return __uint_as_float(u);
}
__device__ __forceinline__ uint32_t tf32u(float x) {
    uint32_t u;
    asm("cvt.rna.tf32.f32 %0, %1;" : "=r"(u) : "f"(x));
    return u;
}

__device__ __forceinline__ void cp16(uint32_t saddr, const float* gaddr) {
    asm volatile("cp.async.cg.shared.global [%0], [%1], 16;"
                 :: "r"(saddr), "l"(gaddr));
}
__device__ __forceinline__ void cp_commit() {
    asm volatile("cp.async.commit_group;");
}

__device__ __forceinline__ float fex2(float x) {
    float r;
    asm("ex2.approx.f32 %0, %1;" : "=f"(r) : "f"(x));
    return r;
}

// D += A(16x8 tf32) * B(8x8 tf32), fp32 accum.
__device__ __forceinline__ void mma8(float* c, const uint32_t* a,
                                     uint32_t b0, uint32_t b1) {
    asm volatile(
        "mma.sync.aligned.m16n8k8.row.col.f32.tf32.tf32.f32 "
        "{%0,%1,%2,%3}, {%4,%5,%6,%7}, {%8,%9}, {%0,%1,%2,%3};"
        : "+f"(c[0]), "+f"(c[1]), "+f"(c[2]), "+f"(c[3])
        : "r"(a[0]), "r"(a[1]), "r"(a[2]), "r"(a[3]), "r"(b0), "r"(b1));
}

// ---------------------------------------------------------------------------
// QKV projection GEMM on tf32 tensor cores.
// out[m][n] = sum_k X[m][k] * W[k][n];  M=16384, K=1024, N=128.
// Grid (M/128, 3). 256 threads = 8 warps, warp tile 32(m) x 64(n), BK=32,
// double-buffered cp.async. Inputs rounded to tf32 (rna) at fragment load.
// ---------------------------------------------------------------------------
#define AST 36      // A smem row stride (floats), ==4 mod 32 -> conflict-free
#define BST 136     // B smem row stride (floats), ==8 mod 32 -> conflict-free
#define A_FL (128 * AST)
#define B_FL (32 * BST)

__global__ __launch_bounds__(256) void qkv_mma_kernel(
    const float* __restrict__ X,
    const float* __restrict__ Wq,
    const float* __restrict__ Wk,
    const float* __restrict__ Wv)
{
    extern __shared__ float smem[];
    float* sA0 = smem;
    float* sA1 = sA0 + A_FL;
    float* sB0 = sA1 + A_FL;
    float* sB1 = sB0 + B_FL;

    const int mblk = blockIdx.x;
    const int proj = blockIdx.y;
    const float* __restrict__ W = (proj == 0) ? Wq : (proj == 1) ? Wk : Wv;
    float* __restrict__ out     = (proj == 0) ? g_q : (proj == 1) ? g_k : g_v;

    const int tid  = threadIdx.x;
    const int wid  = tid >> 5;
    const int lane = tid & 31;
    const int g    = lane >> 2;       // 0..7
    const int tg   = lane & 3;        // 0..3
    const int wm   = wid & 3;         // 0..3 : m position
    const int wn   = wid >> 2;        // 0..1 : n position

    const uint32_t sA0a = (uint32_t)__cvta_generic_to_shared(sA0);
    const uint32_t sA1a = (uint32_t)__cvta_generic_to_shared(sA1);
    const uint32_t sB0a = (uint32_t)__cvta_generic_to_shared(sB0);
    const uint32_t sB1a = (uint32_t)__cvta_generic_to_shared(sB1);

    const float* Xb = X + (size_t)mblk * 128 * CC;

    // load chunk kc into buffer (A: 128x32, B: 32x128)
    auto issue_chunk = [&](int kc, uint32_t sAa, uint32_t sBa) {
#pragma unroll
        for (int it = 0; it < 4; it++) {
            int f  = tid + it * 256;        // 1024 float4
            int r  = f >> 3;                // 0..127
            int c4 = f & 7;                 // 0..7
            cp16(sAa + (r * AST + c4 * 4) * 4, Xb + (size_t)r * CC + kc * 32 + c4 * 4);
        }
#pragma unroll
        for (int it = 0; it < 4; it++) {
            int f  = tid + it * 256;        // 1024 float4
            int r  = f >> 5;                // 0..31
            int c4 = f & 31;                // 0..31
            cp16(sBa + (r * BST + c4 * 4) * 4, W + (size_t)(kc * 32 + r) * HH + c4 * 4);
        }
        cp_commit();
    };

    float acc[2][8][4];
#pragma unroll
    for (int i = 0; i < 2; i++)
#pragma unroll
        for (int n = 0; n < 8; n++)
#pragma unroll
            for (int v = 0; v < 4; v++) acc[i][n][v] = 0.0f;

    issue_chunk(0, sA0a, sB0a);

    for (int kc = 0; kc < 32; kc++) {
        const float* aB = (kc & 1) ? sA1 : sA0;
        const float* bB = (kc & 1) ? sB1 : sB0;
        if (kc + 1 < 32)
            issue_chunk(kc + 1, (kc & 1) ? sA0a : sA1a, (kc & 1) ? sB0a : sB1a);

        asm volatile("cp.async.wait_group %0;" :: "n"(1));
        // when kc+1 was issued, 1 group may remain pending (the prefetch);
        // when kc==31 nothing was issued, group 0 already drained earlier.
        if (kc + 1 >= 32) asm volatile("cp.async.wait_group 0;");
        __syncthreads();

#pragma unroll
        for (int ks = 0; ks < 4; ks++) {
            uint32_t af[2][4];
#pragma unroll
            for (int i = 0; i < 2; i++) {
                const int base = (wm * 32 + i * 16 + g) * AST + ks * 8 + tg;
                af[i][0] = tf32u(aB[base]);
                af[i][1] = tf32u(aB[base + 8 * AST]);
                af[i][2] = tf32u(aB[base + 4]);
                af[i][3] = tf32u(aB[base + 8 * AST + 4]);
            }
#pragma unroll
            for (int n = 0; n < 8; n++) {
                const int base = (ks * 8 + tg) * BST + wn * 64 + n * 8 + g;
                uint32_t b0 = tf32u(bB[base]);
                uint32_t b1 = tf32u(bB[base + 4 * BST]);
                mma8(acc[0][n], af[0], b0, b1);
                mma8(acc[1][n], af[1], b0, b1);
            }
        }
        __syncthreads();
    }

    // epilogue: tf32-round outputs (attention consumes them as exact tf32).
#pragma unroll
    for (int i = 0; i < 2; i++) {
        const int r0 = mblk * 128 + wm * 32 + i * 16 + g;
#pragma unroll
        for (int n = 0; n < 8; n++) {
            const int col = wn * 64 + n * 8 + 2 * tg;
            float* d0 = out + (size_t)r0 * HH + col;
            *(float2*)d0 = make_float2(tf32r(acc[i][n][0]), tf32r(acc[i][n][1]));
            float* d1 = d0 + 8 * HH;
            *(float2*)d1 = make_float2(tf32r(acc[i][n][2]), tf32r(acc[i][n][3]));
        }
    }
}

// ---------------------------------------------------------------------------
// Causal flash attention with mma.sync tf32 tensor cores. (unchanged from R2)
// ---------------------------------------------------------------------------
#define KST 132
#define VST 136
#define PST 68

__global__ __launch_bounds__(128) void attn_mma_kernel(float* __restrict__ Out)
{
    extern __shared__ float smem[];
    float* sQ  = smem;
    float* sK0 = sQ  + 64 * KST;
    float* sV0 = sK0 + 64 * KST;
    float* sK1 = sV0 + 64 * VST;
    float* sV1 = sK1 + 64 * KST;
    float* sP  = sV1 + 64 * VST;

    const int qt   = (int)gridDim.x - 1 - blockIdx.x;
    const int b    = blockIdx.y;
    const int tid  = threadIdx.x;
    const int wid  = tid >> 5;
    const int lane = tid & 31;
    const int g    = lane >> 2;
    const int tg   = lane & 3;

    const uint32_t sQa  = (uint32_t)__cvta_generic_to_shared(sQ);
    const uint32_t sK0a = (uint32_t)__cvta_generic_to_shared(sK0);
    const uint32_t sV0a = (uint32_t)__cvta_generic_to_shared(sV0);
    const uint32_t sK1a = (uint32_t)__cvta_generic_to_shared(sK1);
    const uint32_t sV1a = (uint32_t)__cvta_generic_to_shared(sV1);

    const float* Qb = g_q + ((size_t)b * TT + (size_t)qt * 64) * HH;
    const float* Kb = g_k + ((size_t)b * TT) * HH;
    const float* Vb = g_v + ((size_t)b * TT) * HH;
#pragma unroll
    for (int it = 0; it < 16; it++) {
        int f  = tid + it * 128;
        int r  = f >> 5;
        int c4 = f & 31;
        cp16(sQa + (r * KST + c4 * 4) * 4, Qb + r * HH + c4 * 4);
    }
#pragma unroll
    for (int it = 0; it < 16; it++) {
        int f  = tid + it * 128;
        int r  = f >> 5;
        int c4 = f & 31;
        cp16(sK0a + (r * KST + c4 * 4) * 4, Kb + r * HH + c4 * 4);
        cp16(sV0a + (r * VST + c4 * 4) * 4, Vb + r * HH + c4 * 4);
    }
    cp_commit();
    asm volatile("cp.async.wait_group 0;");
    __syncthreads();

    uint32_t qa[16][4];
#pragma unroll
    for (int ks = 0; ks < 16; ks++) {
        const int r0 = (16 * wid + g) * KST + ks * 8 + tg;
        qa[ks][0] = __float_as_uint(sQ[r0]);
        qa[ks][1] = __float_as_uint(sQ[r0 + 8 * KST]);
        qa[ks][2] = __float_as_uint(sQ[r0 + 4]);
        qa[ks][3] = __float_as_uint(sQ[r0 + 8 * KST + 4]);
    }

    float o[16][4];
#pragma unroll
    for (int n = 0; n < 16; n++)
#pragma unroll
        for (int v = 0; v < 4; v++) o[n][v] = 0.0f;
    float m0 = -1e30f, m1 = -1e30f, l0 = 0.0f, l1 = 0.0f;

    const float SCL = 0.08838834764831845f * 1.4426950408889634f;

    for (int j = 0; j <= qt; j++) {
        if (j < qt) {
            const float* Kn = g_k + ((size_t)b * TT + (size_t)(j + 1) * 64) * HH;
            const float* Vn = g_v + ((size_t)b * TT + (size_t)(j + 1) * 64) * HH;
            uint32_t ska = ((j + 1) & 1) ? sK1a : sK0a;
            uint32_t sva = ((j + 1) & 1) ? sV1a : sV0a;
#pragma unroll
            for (int it = 0; it < 16; it++) {
                int f  = tid + it * 128;
                int r  = f >> 5;
                int c4 = f & 31;
                cp16(ska + (r * KST + c4 * 4) * 4, Kn + r * HH + c4 * 4);
                cp16(sva + (r * VST + c4 * 4) * 4, Vn + r * HH + c4 * 4);
            }
            cp_commit();
        }
        if (j > 0) {
            if (j < qt) asm volatile("cp.async.wait_group 1;");
            else        asm volatile("cp.async.wait_group 0;");
            __syncthreads();
        }

        const float* kb = (j & 1) ? sK1 : sK0;
        const float* vb = (j & 1) ? sV1 : sV0;

        float c[8][4];
#pragma unroll
        for (int n = 0; n < 8; n++)
#pragma unroll
            for (int v = 0; v < 4; v++) c[n][v] = 0.0f;

#pragma unroll
        for (int ks = 0; ks < 16; ks++) {
#pragma unroll
            for (int n = 0; n < 8; n++) {
                const int base = (n * 8 + g) * KST + ks * 8 + tg;
                uint32_t b0 = __float_as_uint(kb[base]);
                uint32_t b1 = __float_as_uint(kb[base + 4]);
                mma8(c[n], qa[ks], b0, b1);
            }
        }

#pragma unroll
        for (int n = 0; n < 8; n++)
#pragma unroll
            for (int v = 0; v < 4; v++) c[n][v] *= SCL;

        if (j == qt) {
            const int r0 = 16 * wid + g;
            const int r1 = r0 + 8;
#pragma unroll
            for (int n = 0; n < 8; n++) {
                const int col = 8 * n + 2 * tg;
                if (col     > r0) c[n][0] = -1e30f;
                if (col + 1 > r0) c[n][1] = -1e30f;
                if (col     > r1) c[n][2] = -1e30f;
                if (col + 1 > r1) c[n][3] = -1e30f;
            }
        }

        float rm0 = -1e30f, rm1 = -1e30f;
#pragma unroll
        for (int n = 0; n < 8; n++) {
            rm0 = fmaxf(rm0, fmaxf(c[n][0], c[n][1]));
            rm1 = fmaxf(rm1, fmaxf(c[n][2], c[n][3]));
        }
        rm0 = fmaxf(rm0, __shfl_xor_sync(0xffffffffu, rm0, 1));
        rm0 = fmaxf(rm0, __shfl_xor_sync(0xffffffffu, rm0, 2));
        rm1 = fmaxf(rm1, __shfl_xor_sync(0xffffffffu, rm1, 1));
        rm1 = fmaxf(rm1, __shfl_xor_sync(0xffffffffu, rm1, 2));

        const float m0n = fmaxf(m0, rm0);
        const float m1n = fmaxf(m1, rm1);
        const float a0  = fex2(m0 - m0n);
        const float a1  = fex2(m1 - m1n);

        float rs0 = 0.0f, rs1 = 0.0f;
#pragma unroll
        for (int n = 0; n < 8; n++) {
            c[n][0] = fex2(c[n][0] - m0n);
            c[n][1] = fex2(c[n][1] - m0n);
            c[n][2] = fex2(c[n][2] - m1n);
            c[n][3] = fex2(c[n][3] - m1n);
            rs0 += c[n][0] + c[n][1];
            rs1 += c[n][2] + c[n][3];
        }
        rs0 += __shfl_xor_sync(0xffffffffu, rs0, 1);
        rs0 += __shfl_xor_sync(0xffffffffu, rs0, 2);
        rs1 += __shfl_xor_sync(0xffffffffu, rs1, 1);
        rs1 += __shfl_xor_sync(0xffffffffu, rs1, 2);

        l0 = l0 * a0 + rs0;
        l1 = l1 * a1 + rs1;
        m0 = m0n;
        m1 = m1n;

#pragma unroll
        for (int n = 0; n < 16; n++) {
            o[n][0] *= a0; o[n][1] *= a0;
            o[n][2] *= a1; o[n][3] *= a1;
        }

        __syncwarp();
        {
            const int r0 = 16 * wid + g;
#pragma unroll
            for (int n = 0; n < 8; n++) {
                const int col = 8 * n + 2 * tg;
                *(float2*)&sP[r0 * PST + col] =
                    make_float2(tf32r(c[n][0]), tf32r(c[n][1]));
                *(float2*)&sP[(r0 + 8) * PST + col] =
                    make_float2(tf32r(c[n][2]), tf32r(c[n][3]));
            }
        }
        __syncwarp();

#pragma unroll
        for (int kk = 0; kk < 8; kk++) {
            uint32_t pa[4];
            const int pr = (16 * wid + g) * PST + kk * 8 + tg;
            pa[0] = __float_as_uint(sP[pr]);
            pa[1] = __float_as_uint(sP[pr + 8 * PST]);
            pa[2] = __float_as_uint(sP[pr + 4]);
            pa[3] = __float_as_uint(sP[pr + 8 * PST + 4]);
#pragma unroll
            for (int n = 0; n < 16; n++) {
                const int base = (kk * 8 + tg) * VST + 8 * n + g;
                uint32_t b0 = __float_as_uint(vb[base]);
                uint32_t b1 = __float_as_uint(vb[base + 4 * VST]);
                mma8(o[n], pa, b0, b1);
            }
        }
        __syncthreads();
    }

    const float inv0 = 1.0f / l0;
    const float inv1 = 1.0f / l1;
    const int r0 = qt * 64 + 16 * wid + g;
    float* p0 = Out + ((size_t)b * TT + r0) * HH;
    float* p1 = p0 + 8 * HH;
#pragma unroll
    for (int n = 0; n < 16; n++) {
        const int col = 8 * n + 2 * tg;
        *(float2*)(p0 + col) = make_float2(o[n][0] * inv0, o[n][1] * inv0);
        *(float2*)(p1 + col) = make_float2(o[n][2] * inv1, o[n][3] * inv1);
    }
}

// ---------------------------------------------------------------------------
extern "C" void kernel_launch(void* const* d_in, const int* in_sizes, int n_in,
                              void* d_out, int out_size)
{
    const float* x  = (const float*)d_in[0];
    const float* Wq = (const float*)d_in[1];
    const float* Wk = (const float*)d_in[2];
    const float* Wv = (const float*)d_in[3];
    float* out = (float*)d_out;

    (void)in_sizes; (void)n_in; (void)out_size;

    const int gemm_smem = (2 * A_FL + 2 * B_FL) * (int)sizeof(float);
    cudaFuncSetAttribute(qkv_mma_kernel,
                         cudaFuncAttributeMaxDynamicSharedMemorySize, gemm_smem);
    qkv_mma_kernel<<<dim3((BB * TT) / 128, 3), 256, gemm_smem>>>(x, Wq, Wk, Wv);

    const int smem_bytes = 64 * (3 * KST + 2 * VST + PST) * (int)sizeof(float);
    cudaFuncSetAttribute(attn_mma_kernel,
                         cudaFuncAttributeMaxDynamicSharedMemorySize, smem_bytes);
    attn_mma_kernel<<<dim3(TT / 64, BB), 128, smem_bytes>>>(out);
}

// round 4
// speedup vs baseline: 5.2894x; 1.0512x over previous
#include <cuda_runtime.h>
#include <cstdint>
#include <cstddef>

#define BB 8
#define TT 2048
#define CC 1024
#define HH 128

// Scratch (device globals — no runtime alloc).
__device__ float g_q[BB * TT * HH];
__device__ float g_k[BB * TT * HH];
__device__ float g_v[BB * TT * HH];
__device__ float g_wt[3 * CC * HH];   // tf32-pre-rounded weights

// ---------------------------------------------------------------------------
// Helpers
// ---------------------------------------------------------------------------
__device__ __forceinline__ float tf32r(float x) {
    uint32_t u;
    asm("cvt.rna.tf32.f32 %0, %1;" : "=r"(u) : "f"(x));
    return __uint_as_float(u);
}
__device__ __forceinline__ uint32_t tf32u(float x) {
    uint32_t u;
    asm("cvt.rna.tf32.f32 %0, %1;" : "=r"(u) : "f"(x));
    return u;
}
__device__ __forceinline__ void cp16(uint32_t saddr, const float* gaddr) {
    asm volatile("cp.async.cg.shared.global [%0], [%1], 16;"
                 :: "r"(saddr), "l"(gaddr));
}
__device__ __forceinline__ void cp_commit() {
    asm volatile("cp.async.commit_group;");
}
__device__ __forceinline__ float fex2(float x) {
    float r;
    asm("ex2.approx.f32 %0, %1;" : "=f"(r) : "f"(x));
    return r;
}
// D += A(16x8 tf32) * B(8x8 tf32), fp32 accum.
__device__ __forceinline__ void mma8(float* c, const uint32_t* a,
                                     uint32_t b0, uint32_t b1) {
    asm volatile(
        "mma.sync.aligned.m16n8k8.row.col.f32.tf32.tf32.f32 "
        "{%0,%1,%2,%3}, {%4,%5,%6,%7}, {%8,%9}, {%0,%1,%2,%3};"
        : "+f"(c[0]), "+f"(c[1]), "+f"(c[2]), "+f"(c[3])
        : "r"(a[0]), "r"(a[1]), "r"(a[2]), "r"(a[3]), "r"(b0), "r"(b1));
}

// ---------------------------------------------------------------------------
// W prepass: round all three weight matrices to tf32 once.
// grid (CC*HH/4/256 = 128, 3), 256 threads.
// ---------------------------------------------------------------------------
__global__ __launch_bounds__(256) void round_w_kernel(
    const float* __restrict__ Wq,
    const float* __restrict__ Wk,
    const float* __restrict__ Wv)
{
    const int proj = blockIdx.y;
    const float* __restrict__ W = (proj == 0) ? Wq : (proj == 1) ? Wk : Wv;
    const int i = blockIdx.x * 256 + threadIdx.x;          // float4 index
    float4 v = ((const float4*)W)[i];
    float4 r = make_float4(tf32r(v.x), tf32r(v.y), tf32r(v.z), tf32r(v.w));
    ((float4*)(g_wt + (size_t)proj * CC * HH))[i] = r;
}

// ---------------------------------------------------------------------------
// QKV projection GEMM on tf32 tensor cores.
// M=16384, K=1024, N=128; grid (128, 3), 256 thr, warp tile 32x64, BK=32.
// B operand pre-rounded (raw bit loads); A rounded at fragment load.
// ---------------------------------------------------------------------------
#define AST 36
#define BST 136
#define A_FL (128 * AST)
#define B_FL (32 * BST)

__global__ __launch_bounds__(256, 2) void qkv_mma_kernel(
    const float* __restrict__ X)
{
    extern __shared__ float smem[];
    float* sA0 = smem;
    float* sA1 = sA0 + A_FL;
    float* sB0 = sA1 + A_FL;
    float* sB1 = sB0 + B_FL;

    const int mblk = blockIdx.x;
    const int proj = blockIdx.y;
    const float* __restrict__ W = g_wt + (size_t)proj * CC * HH;
    float* __restrict__ out     = (proj == 0) ? g_q : (proj == 1) ? g_k : g_v;

    const int tid  = threadIdx.x;
    const int wid  = tid >> 5;
    const int lane = tid & 31;
    const int g    = lane >> 2;
    const int tg   = lane & 3;
    const int wm   = wid & 3;
    const int wn   = wid >> 2;

    const uint32_t sA0a = (uint32_t)__cvta_generic_to_shared(sA0);
    const uint32_t sA1a = (uint32_t)__cvta_generic_to_shared(sA1);
    const uint32_t sB0a = (uint32_t)__cvta_generic_to_shared(sB0);
    const uint32_t sB1a = (uint32_t)__cvta_generic_to_shared(sB1);

    const float* Xb = X + (size_t)mblk * 128 * CC;

    auto issue_chunk = [&](int kc, uint32_t sAa, uint32_t sBa) {
#pragma unroll
        for (int it = 0; it < 4; it++) {
            int f  = tid + it * 256;
            int r  = f >> 3;
            int c4 = f & 7;
            cp16(sAa + (r * AST + c4 * 4) * 4, Xb + (size_t)r * CC + kc * 32 + c4 * 4);
        }
#pragma unroll
        for (int it = 0; it < 4; it++) {
            int f  = tid + it * 256;
            int r  = f >> 5;
            int c4 = f & 31;
            cp16(sBa + (r * BST + c4 * 4) * 4, W + (size_t)(kc * 32 + r) * HH + c4 * 4);
        }
        cp_commit();
    };

    float acc[2][8][4];
#pragma unroll
    for (int i = 0; i < 2; i++)
#pragma unroll
        for (int n = 0; n < 8; n++)
#pragma unroll
            for (int v = 0; v < 4; v++) acc[i][n][v] = 0.0f;

    issue_chunk(0, sA0a, sB0a);

    for (int kc = 0; kc < 32; kc++) {
        const float* aB = (kc & 1) ? sA1 : sA0;
        const float* bB = (kc & 1) ? sB1 : sB0;
        if (kc + 1 < 32)
            issue_chunk(kc + 1, (kc & 1) ? sA0a : sA1a, (kc & 1) ? sB0a : sB1a);

        asm volatile("cp.async.wait_group %0;" :: "n"(1));
        if (kc + 1 >= 32) asm volatile("cp.async.wait_group 0;");
        __syncthreads();

#pragma unroll
        for (int ks = 0; ks < 4; ks++) {
            uint32_t af[2][4];
#pragma unroll
            for (int i = 0; i < 2; i++) {
                const int base = (wm * 32 + i * 16 + g) * AST + ks * 8 + tg;
                af[i][0] = tf32u(aB[base]);
                af[i][1] = tf32u(aB[base + 8 * AST]);
                af[i][2] = tf32u(aB[base + 4]);
                af[i][3] = tf32u(aB[base + 8 * AST + 4]);
            }
#pragma unroll
            for (int n = 0; n < 8; n++) {
                const int base = (ks * 8 + tg) * BST + wn * 64 + n * 8 + g;
                uint32_t b0 = __float_as_uint(bB[base]);
                uint32_t b1 = __float_as_uint(bB[base + 4 * BST]);
                mma8(acc[0][n], af[0], b0, b1);
                mma8(acc[1][n], af[1], b0, b1);
            }
        }
        __syncthreads();
    }

#pragma unroll
    for (int i = 0; i < 2; i++) {
        const int r0 = mblk * 128 + wm * 32 + i * 16 + g;
#pragma unroll
        for (int n = 0; n < 8; n++) {
            const int col = wn * 64 + n * 8 + 2 * tg;
            float* d0 = out + (size_t)r0 * HH + col;
            *(float2*)d0 = make_float2(tf32r(acc[i][n][0]), tf32r(acc[i][n][1]));
            float* d1 = d0 + 8 * HH;
            *(float2*)d1 = make_float2(tf32r(acc[i][n][2]), tf32r(acc[i][n][3]));
        }
    }
}

// ---------------------------------------------------------------------------
// Causal flash attention, tf32 mma.sync, 2 CTAs/SM.
// Single-buffered K/V with split waits; P fragments via intra-quad shuffles.
// Grid (32, 8): (qt, b) remapped for 2-CTA/SM load balance.
// ---------------------------------------------------------------------------
#define KST 132
#define VST 136

__global__ __launch_bounds__(128) void attn_mma_kernel(float* __restrict__ Out)
{
    extern __shared__ float smem[];
    float* sQ = smem;                 // 64*132
    float* sK = sQ + 64 * KST;        // 64*132
    float* sV = sK + 64 * KST;        // 64*136

    // (qt, b) mapping: paired bids (lin, lin+148) share an SM and sum to 28
    // steps; unpaired bids 108..147 take the heaviest tiles (qt 27..31).
    const int lin = blockIdx.x + 32 * blockIdx.y;
    int qt, b;
    if (lin >= 108 && lin < 148) {
        int t = lin - 108; qt = 27 + (t >> 3); b = t & 7;
    } else if (lin < 108) {
        qt = lin % 27; b = lin / 27;
    } else {
        int t = lin - 148; qt = 26 - (t % 27); b = 4 + t / 27;
    }

    const int tid  = threadIdx.x;
    const int wid  = tid >> 5;
    const int lane = tid & 31;
    const int g    = lane >> 2;
    const int tg   = lane & 3;

    const uint32_t sQa = (uint32_t)__cvta_generic_to_shared(sQ);
    const uint32_t sKa = (uint32_t)__cvta_generic_to_shared(sK);
    const uint32_t sVa = (uint32_t)__cvta_generic_to_shared(sV);

    const float* Qb = g_q + ((size_t)b * TT + (size_t)qt * 64) * HH;
    const float* Kb = g_k + ((size_t)b * TT) * HH;
    const float* Vb = g_v + ((size_t)b * TT) * HH;

    // prologue: group A = {Q, K0}, group B = {V0}
#pragma unroll
    for (int it = 0; it < 16; it++) {
        int f  = tid + it * 128;
        int r  = f >> 5;
        int c4 = f & 31;
        cp16(sQa + (r * KST + c4 * 4) * 4, Qb + r * HH + c4 * 4);
        cp16(sKa + (r * KST + c4 * 4) * 4, Kb + r * HH + c4 * 4);
    }
    cp_commit();
#pragma unroll
    for (int it = 0; it < 16; it++) {
        int f  = tid + it * 128;
        int r  = f >> 5;
        int c4 = f & 31;
        cp16(sVa + (r * VST + c4 * 4) * 4, Vb + r * HH + c4 * 4);
    }
    cp_commit();

    asm volatile("cp.async.wait_group 1;");   // Q + K0 arrived
    __syncthreads();

    uint32_t qa[16][4];
#pragma unroll
    for (int ks = 0; ks < 16; ks++) {
        const int r0 = (16 * wid + g) * KST + ks * 8 + tg;
        qa[ks][0] = __float_as_uint(sQ[r0]);
        qa[ks][1] = __float_as_uint(sQ[r0 + 8 * KST]);
        qa[ks][2] = __float_as_uint(sQ[r0 + 4]);
        qa[ks][3] = __float_as_uint(sQ[r0 + 8 * KST + 4]);
    }

    float o[16][4];
#pragma unroll
    for (int n = 0; n < 16; n++)
#pragma unroll
        for (int v = 0; v < 4; v++) o[n][v] = 0.0f;
    float m0 = -1e30f, m1 = -1e30f, l0 = 0.0f, l1 = 0.0f;

    const float SCL = 0.08838834764831845f * 1.4426950408889634f;
    const int src0 = (lane & ~3) | (tg >> 1);
    const int src1 = src0 + 2;
    const bool odd = (tg & 1);

    for (int j = 0; j <= qt; j++) {
        if (j > 0) {                       // K(j) arrived (V(j) may be pending)
            asm volatile("cp.async.wait_group 1;");
            __syncthreads();
        }

        // ----- S = Q K^T -----
        float c[8][4];
#pragma unroll
        for (int n = 0; n < 8; n++)
#pragma unroll
            for (int v = 0; v < 4; v++) c[n][v] = 0.0f;

#pragma unroll
        for (int ks = 0; ks < 16; ks++) {
#pragma unroll
            for (int n = 0; n < 8; n++) {
                const int base = (n * 8 + g) * KST + ks * 8 + tg;
                uint32_t b0 = __float_as_uint(sK[base]);
                uint32_t b1 = __float_as_uint(sK[base + 4]);
                mma8(c[n], qa[ks], b0, b1);
            }
        }

        __syncthreads();                   // all warps done reading sK
        if (j < qt) {                      // K(j+1) flies over softmax + PV
            const float* Kn = g_k + ((size_t)b * TT + (size_t)(j + 1) * 64) * HH;
#pragma unroll
            for (int it = 0; it < 16; it++) {
                int f  = tid + it * 128;
                int r  = f >> 5;
                int c4 = f & 31;
                cp16(sKa + (r * KST + c4 * 4) * 4, Kn + r * HH + c4 * 4);
            }
            cp_commit();
        }

        // ----- scale + causal mask -----
#pragma unroll
        for (int n = 0; n < 8; n++)
#pragma unroll
            for (int v = 0; v < 4; v++) c[n][v] *= SCL;

        if (j == qt) {
            const int r0 = 16 * wid + g;
            const int r1 = r0 + 8;
#pragma unroll
            for (int n = 0; n < 8; n++) {
                const int col = 8 * n + 2 * tg;
                if (col     > r0) c[n][0] = -1e30f;
                if (col + 1 > r0) c[n][1] = -1e30f;
                if (col     > r1) c[n][2] = -1e30f;
                if (col + 1 > r1) c[n][3] = -1e30f;
            }
        }

        // ----- online softmax -----
        float rm0 = -1e30f, rm1 = -1e30f;
#pragma unroll
        for (int n = 0; n < 8; n++) {
            rm0 = fmaxf(rm0, fmaxf(c[n][0], c[n][1]));
            rm1 = fmaxf(rm1, fmaxf(c[n][2], c[n][3]));
        }
        rm0 = fmaxf(rm0, __shfl_xor_sync(0xffffffffu, rm0, 1));
        rm0 = fmaxf(rm0, __shfl_xor_sync(0xffffffffu, rm0, 2));
        rm1 = fmaxf(rm1, __shfl_xor_sync(0xffffffffu, rm1, 1));
        rm1 = fmaxf(rm1, __shfl_xor_sync(0xffffffffu, rm1, 2));

        const float m0n = fmaxf(m0, rm0);
        const float m1n = fmaxf(m1, rm1);
        const float a0  = fex2(m0 - m0n);
        const float a1  = fex2(m1 - m1n);

        float rs0 = 0.0f, rs1 = 0.0f;
#pragma unroll
        for (int n = 0; n < 8; n++) {
            c[n][0] = fex2(c[n][0] - m0n);
            c[n][1] = fex2(c[n][1] - m0n);
            c[n][2] = fex2(c[n][2] - m1n);
            c[n][3] = fex2(c[n][3] - m1n);
            rs0 += c[n][0] + c[n][1];
            rs1 += c[n][2] + c[n][3];
        }
        rs0 += __shfl_xor_sync(0xffffffffu, rs0, 1);
        rs0 += __shfl_xor_sync(0xffffffffu, rs0, 2);
        rs1 += __shfl_xor_sync(0xffffffffu, rs1, 1);
        rs1 += __shfl_xor_sync(0xffffffffu, rs1, 2);

        l0 = l0 * a0 + rs0;
        l1 = l1 * a1 + rs1;
        m0 = m0n;
        m1 = m1n;

#pragma unroll
        for (int n = 0; n < 16; n++) {
            o[n][0] *= a0; o[n][1] *= a0;
            o[n][2] *= a1; o[n][3] *= a1;
        }

        // round P to tf32 (same numerics as the old smem-staged path)
#pragma unroll
        for (int n = 0; n < 8; n++)
#pragma unroll
            for (int v = 0; v < 4; v++) c[n][v] = tf32r(c[n][v]);

        // ----- V(j) arrived? -----
        if (j < qt) asm volatile("cp.async.wait_group 1;");
        else        asm volatile("cp.async.wait_group 0;");
        __syncthreads();

        // ----- O += P V, P fragments via intra-quad shuffles -----
#pragma unroll
        for (int kk = 0; kk < 8; kk++) {
            float v00 = __shfl_sync(0xffffffffu, c[kk][0], src0);
            float v01 = __shfl_sync(0xffffffffu, c[kk][1], src0);
            float v10 = __shfl_sync(0xffffffffu, c[kk][2], src0);
            float v11 = __shfl_sync(0xffffffffu, c[kk][3], src0);
            float v20 = __shfl_sync(0xffffffffu, c[kk][0], src1);
            float v21 = __shfl_sync(0xffffffffu, c[kk][1], src1);
            float v30 = __shfl_sync(0xffffffffu, c[kk][2], src1);
            float v31 = __shfl_sync(0xffffffffu, c[kk][3], src1);
            uint32_t pa[4];
            pa[0] = __float_as_uint(odd ? v01 : v00);
            pa[1] = __float_as_uint(odd ? v11 : v10);
            pa[2] = __float_as_uint(odd ? v21 : v20);
            pa[3] = __float_as_uint(odd ? v31 : v30);
#pragma unroll
            for (int n = 0; n < 16; n++) {
                const int base = (kk * 8 + tg) * VST + 8 * n + g;
                uint32_t b0 = __float_as_uint(sV[base]);
                uint32_t b1 = __float_as_uint(sV[base + 4 * VST]);
                mma8(o[n], pa, b0, b1);
            }
        }

        __syncthreads();                   // all warps done reading sV
        if (j < qt) {                      // V(j+1) flies over next S
            const float* Vn = g_v + ((size_t)b * TT + (size_t)(j + 1) * 64) * HH;
#pragma unroll
            for (int it = 0; it < 16; it++) {
                int f  = tid + it * 128;
                int r  = f >> 5;
                int c4 = f & 31;
                cp16(sVa + (r * VST + c4 * 4) * 4, Vn + r * HH + c4 * 4);
            }
            cp_commit();
        }
    }

    // ----- epilogue -----
    const float inv0 = 1.0f / l0;
    const float inv1 = 1.0f / l1;
    const int r0 = qt * 64 + 16 * wid + g;
    float* p0 = Out + ((size_t)b * TT + r0) * HH;
    float* p1 = p0 + 8 * HH;
#pragma unroll
    for (int n = 0; n < 16; n++) {
        const int col = 8 * n + 2 * tg;
        *(float2*)(p0 + col) = make_float2(o[n][0] * inv0, o[n][1] * inv0);
        *(float2*)(p1 + col) = make_float2(o[n][2] * inv1, o[n][3] * inv1);
    }
}

// ---------------------------------------------------------------------------
extern "C" void kernel_launch(void* const* d_in, const int* in_sizes, int n_in,
                              void* d_out, int out_size)
{
    const float* x  = (const float*)d_in[0];
    const float* Wq = (const float*)d_in[1];
    const float* Wk = (const float*)d_in[2];
    const float* Wv = (const float*)d_in[3];
    float* out = (float*)d_out;

    (void)in_sizes; (void)n_in; (void)out_size;

    round_w_kernel<<<dim3((CC * HH) / 4 / 256, 3), 256>>>(Wq, Wk, Wv);

    const int gemm_smem = (2 * A_FL + 2 * B_FL) * (int)sizeof(float);
    cudaFuncSetAttribute(qkv_mma_kernel,
                         cudaFuncAttributeMaxDynamicSharedMemorySize, gemm_smem);
    qkv_mma_kernel<<<dim3((BB * TT) / 128, 3), 256, gemm_smem>>>(x);

    const int attn_smem = 64 * (2 * KST + VST) * (int)sizeof(float);
    cudaFuncSetAttribute(attn_mma_kernel,
                         cudaFuncAttributeMaxDynamicSharedMemorySize, attn_smem);
    attn_mma_kernel<<<dim3(TT / 64, BB), 128, attn_smem>>>(out);
}